// round 13
// baseline (speedup 1.0000x reference)
#include <cuda_runtime.h>
#include <cuda_fp16.h>
#include <cuda_bf16.h>
#include <mma.h>
#include <cstdint>
#include <math.h>

using namespace nvcuda;

// ---------------------------------------------------------------------------
// GAT graph encoder, 2 layers. CSR-by-dst per call; softmax max cancels.
// R8 + WMMA bf16-split tensor GEMM (fp32-accurate hi/lo split, HMMA path —
// tcgen05 is unreachable: harness compiles via compute_103 virtual arch).
// Attention logits fused in GEMM epilogue. agg/CSR identical to R8.
// ---------------------------------------------------------------------------

#define NMAX 100000
#define EMAX 1600000
#define NEG_SLOPE 0.2f
#define SCAN_CHUNK 4096
#define LDT 136                    // padded leading dim (elems) for smem tiles

typedef unsigned long long ull;

__device__ __half g_h1h[NMAX * 128];   // layer1 features fp16
__device__ __half g_h2h[NMAX * 128];   // layer2 features fp16
__device__ float  g_act1[NMAX * 128];  // layer1 activations (GEMM2 input) fp32
__device__ float  g_asrc1[NMAX * 4];
__device__ float  g_adst1[NMAX * 4];
__device__ float  g_asrc2[NMAX];
__device__ float  g_adst2[NMAX];
__device__ int    g_cnt[NMAX];
__device__ int    g_off[NMAX + 1];
__device__ int    g_pos[NMAX];
__device__ int    g_srcs[EMAX];
__device__ int    g_bsum[64];
__device__ int    g_bpre[64];
__device__ int    g_is64;
// W transposed + bf16 hi/lo split: Wt[n][k] = W[k*128+n], row-major 128x128
__device__ __align__(128) __nv_bfloat16 g_w1h[16384];
__device__ __align__(128) __nv_bfloat16 g_w1l[16384];
__device__ __align__(128) __nv_bfloat16 g_w2h[16384];
__device__ __align__(128) __nv_bfloat16 g_w2l[16384];

// smem layout for the wmma GEMM kernel (bytes)
#define SM_AH   0
#define SM_AL   34816
#define SM_BH   69632
#define SM_BL   104448
#define SM_ATT  139264
#define WG_SMEM (139264 + 1024)
// C (fp32, ldm LDT, 128 rows = 69632 B) aliases [SM_AH, SM_BH)

// --------------------------- edge dtype sniffing ---------------------------
__global__ void detect_kernel(const void* a, int n_nodes) {
    __shared__ int s_bad;
    int i = threadIdx.x;
    if (i == 0) s_bad = 0;
    __syncthreads();
    const ull* p = (const ull*)a;
    if (p[i] >= (ull)n_nodes) atomicAdd(&s_bad, 1);
    __syncthreads();
    if (i == 0) g_is64 = (s_bad == 0) ? 1 : 0;
}

__device__ __forceinline__ int edge_val(const void* a, long long idx) {
    if (g_is64) return (int)((const long long*)a)[idx];
    return ((const int*)a)[idx];
}

// ------------------------------- CSR build ---------------------------------
__global__ void zero_cnt_kernel(int n) {
    int i = blockIdx.x * blockDim.x + threadIdx.x;
    if (i < n) g_cnt[i] = 0;
}

__global__ void hist_kernel(const void* a, int E) {
    int e = blockIdx.x * blockDim.x + threadIdx.x;
    if (e >= E) return;
    int dst = edge_val(a, (long long)E + e);
    atomicAdd(&g_cnt[dst], 1);
}

__global__ void scanA_kernel(int n) {
    __shared__ int wsum[32];
    int b = blockIdx.x, tid = threadIdx.x;
    int lane = tid & 31, warp = tid >> 5;
    int base = b * SCAN_CHUNK + tid * 4;
    int v0 = 0, v1 = 0, v2 = 0, v3 = 0;
    if (base + 3 < n) {
        int4 v = *(const int4*)&g_cnt[base];
        v0 = v.x; v1 = v.y; v2 = v.z; v3 = v.w;
    } else if (base < n) {
        v0 = g_cnt[base];
        if (base + 1 < n) v1 = g_cnt[base + 1];
        if (base + 2 < n) v2 = g_cnt[base + 2];
    }
    int tsum = v0 + v1 + v2 + v3;
    int x = tsum;
    #pragma unroll
    for (int d = 1; d < 32; d <<= 1) {
        int t = __shfl_up_sync(0xffffffffu, x, d);
        if (lane >= d) x += t;
    }
    if (lane == 31) wsum[warp] = x;
    __syncthreads();
    if (warp == 0) {
        int y = wsum[lane];
        #pragma unroll
        for (int d = 1; d < 32; d <<= 1) {
            int t = __shfl_up_sync(0xffffffffu, y, d);
            if (lane >= d) y += t;
        }
        wsum[lane] = y;
    }
    __syncthreads();
    int excl = (warp ? wsum[warp - 1] : 0) + (x - tsum);
    if (base < n) {
        g_off[base] = excl;
        if (base + 1 < n) g_off[base + 1] = excl + v0;
        if (base + 2 < n) g_off[base + 2] = excl + v0 + v1;
        if (base + 3 < n) g_off[base + 3] = excl + v0 + v1 + v2;
    }
    if (tid == 0) g_bsum[b] = wsum[31];
}

__global__ void scanB_kernel(int nblocks, int n) {
    int lane = threadIdx.x;
    int v = (lane < nblocks) ? g_bsum[lane] : 0;
    int x = v;
    #pragma unroll
    for (int d = 1; d < 32; d <<= 1) {
        int t = __shfl_up_sync(0xffffffffu, x, d);
        if (lane >= d) x += t;
    }
    if (lane < nblocks) g_bpre[lane] = x - v;
    if (lane == 31) g_off[n] = x;
}

__global__ void scanC_kernel(int n) {
    int i = blockIdx.x * blockDim.x + threadIdx.x;
    if (i < n) {
        int o = g_off[i] + g_bpre[i >> 12];
        g_off[i] = o;
        g_pos[i] = o;
    }
}

__global__ void scatter_kernel(const void* a, int E) {
    int e = blockIdx.x * blockDim.x + threadIdx.x;
    if (e >= E) return;
    int src = edge_val(a, e);
    int dst = edge_val(a, (long long)E + e);
    int p = atomicAdd(&g_pos[dst], 1);
    g_srcs[p] = src;
}

// ----------------------- W -> transposed bf16 split ------------------------
// Wt[n][k] = W[k*128 + n]; hi/lo bf16 split, plain row-major.
__global__ void prep_w_kernel(const float* __restrict__ W,
                              __nv_bfloat16* __restrict__ Wh,
                              __nv_bfloat16* __restrict__ Wl) {
    int i = blockIdx.x * blockDim.x + threadIdx.x;
    if (i >= 16384) return;
    int k = i >> 7, n = i & 127;
    float v = W[i];
    __nv_bfloat16 hi = __float2bfloat16_rn(v);
    __nv_bfloat16 lo = __float2bfloat16_rn(v - __bfloat162float(hi));
    Wh[n * 128 + k] = hi;
    Wl[n * 128 + k] = lo;
}

// ------------------- WMMA GEMM + attention epilogue ------------------------
// C[128,128] = A[128,128] @ W[128,128] via bf16 split; fp32 accumulate.
// 8 warps, each owns a 32x64 C tile (2x4 wmma 16x16x16 fragments).
template <int HEADS>
__global__ __launch_bounds__(256, 1)
void wmma_gemm_kernel(const float* __restrict__ A,
                      const __nv_bfloat16* __restrict__ WtH,
                      const __nv_bfloat16* __restrict__ WtL,
                      const float* __restrict__ att_src,
                      const float* __restrict__ att_dst,
                      __half* __restrict__ H, int M) {
    extern __shared__ char smem[];
    __nv_bfloat16* sAh = (__nv_bfloat16*)(smem + SM_AH);
    __nv_bfloat16* sAl = (__nv_bfloat16*)(smem + SM_AL);
    __nv_bfloat16* sBh = (__nv_bfloat16*)(smem + SM_BH);
    __nv_bfloat16* sBl = (__nv_bfloat16*)(smem + SM_BL);
    float* satt = (float*)(smem + SM_ATT);   // [0:128) src, [128:256) dst
    float* sC = (float*)smem;                // aliases sAh/sAl after MMA

    int tid = threadIdx.x;
    int row0 = blockIdx.x * 128;

    if (tid < 128) {
        satt[tid] = att_src[tid];
        satt[128 + tid] = att_dst[tid];
    }
    // Wt hi/lo -> smem (ldm LDT)
    for (int i = tid; i < 2048; i += 256) {
        int r = i >> 4, c = (i & 15) * 8;
        *(uint4*)&sBh[r * LDT + c] = *(const uint4*)&WtH[r * 128 + c];
        *(uint4*)&sBl[r * LDT + c] = *(const uint4*)&WtL[r * 128 + c];
    }
    // A -> bf16 hi/lo (ldm LDT)
    for (int i = tid; i < 4096; i += 256) {
        int r = i >> 5, c = (i & 31) * 4;
        float4 v = make_float4(0.f, 0.f, 0.f, 0.f);
        if (row0 + r < M)
            v = *(const float4*)&A[(long long)(row0 + r) * 128 + c];
        float vv[4] = {v.x, v.y, v.z, v.w};
        __nv_bfloat16 hi[4], lo[4];
        #pragma unroll
        for (int q = 0; q < 4; q++) {
            hi[q] = __float2bfloat16_rn(vv[q]);
            lo[q] = __float2bfloat16_rn(vv[q] - __bfloat162float(hi[q]));
        }
        *(uint2*)&sAh[r * LDT + c] = *(uint2*)hi;
        *(uint2*)&sAl[r * LDT + c] = *(uint2*)lo;
    }
    __syncthreads();

    int wid = tid >> 5;
    int wm = wid & 3;       // 4 m-tiles of 32 rows
    int wn = wid >> 2;      // 2 n-tiles of 64 cols

    wmma::fragment<wmma::accumulator, 16, 16, 16, float> acc[2][4];
    #pragma unroll
    for (int i = 0; i < 2; i++)
        #pragma unroll
        for (int j = 0; j < 4; j++) wmma::fill_fragment(acc[i][j], 0.f);

    #pragma unroll
    for (int k0 = 0; k0 < 128; k0 += 16) {
        wmma::fragment<wmma::matrix_a, 16, 16, 16, __nv_bfloat16, wmma::row_major> ah[2], al[2];
        wmma::fragment<wmma::matrix_b, 16, 16, 16, __nv_bfloat16, wmma::col_major> bh[4], bl[4];
        #pragma unroll
        for (int i = 0; i < 2; i++) {
            wmma::load_matrix_sync(ah[i], &sAh[(wm * 32 + i * 16) * LDT + k0], LDT);
            wmma::load_matrix_sync(al[i], &sAl[(wm * 32 + i * 16) * LDT + k0], LDT);
        }
        #pragma unroll
        for (int j = 0; j < 4; j++) {
            wmma::load_matrix_sync(bh[j], &sBh[(wn * 64 + j * 16) * LDT + k0], LDT);
            wmma::load_matrix_sync(bl[j], &sBl[(wn * 64 + j * 16) * LDT + k0], LDT);
        }
        #pragma unroll
        for (int i = 0; i < 2; i++)
            #pragma unroll
            for (int j = 0; j < 4; j++) {
                wmma::mma_sync(acc[i][j], ah[i], bh[j], acc[i][j]);
                wmma::mma_sync(acc[i][j], ah[i], bl[j], acc[i][j]);
                wmma::mma_sync(acc[i][j], al[i], bh[j], acc[i][j]);
            }
    }
    __syncthreads();   // tiles fully consumed; sC may overwrite sAh/sAl

    #pragma unroll
    for (int i = 0; i < 2; i++)
        #pragma unroll
        for (int j = 0; j < 4; j++)
            wmma::store_matrix_sync(&sC[(wm * 32 + i * 16) * LDT + wn * 64 + j * 16],
                                    acc[i][j], LDT, wmma::mem_row_major);
    __syncthreads();

    // Epilogue: each thread handles one half-row (64 cols).
    int lrow = tid >> 1;
    int half = tid & 1;
    int r = row0 + lrow;
    const float* crow = &sC[lrow * LDT + half * 64];

    if (HEADS == 4) {
        // half 0 -> heads 0,1 ; half 1 -> heads 2,3 (32 cols each)
        #pragma unroll
        for (int hh = 0; hh < 2; hh++) {
            int h = half * 2 + hh;
            float ps = 0.f, pd = 0.f;
            #pragma unroll
            for (int c = 0; c < 32; c++) {
                float v = crow[hh * 32 + c];
                ps += v * satt[h * 32 + c];
                pd += v * satt[128 + h * 32 + c];
            }
            if (r < M) {
                g_asrc1[r * 4 + h] = ps;
                g_adst1[r * 4 + h] = pd;
            }
        }
    } else {
        float ps = 0.f, pd = 0.f;
        #pragma unroll
        for (int c = 0; c < 64; c++) {
            float v = crow[c];
            ps += v * satt[half * 64 + c];
            pd += v * satt[128 + half * 64 + c];
        }
        ps += __shfl_xor_sync(0xffffffffu, ps, 1);
        pd += __shfl_xor_sync(0xffffffffu, pd, 1);
        if (r < M && half == 0) {
            g_asrc2[r] = ps;
            g_adst2[r] = pd;
        }
    }
    if (r < M) {
        #pragma unroll
        for (int q = 0; q < 8; q++) {
            __half2 p[4];
            #pragma unroll
            for (int j = 0; j < 4; j++)
                p[j] = __floats2half2_rn(crow[q * 8 + 2 * j], crow[q * 8 + 2 * j + 1]);
            *(uint4*)&H[(long long)r * 128 + half * 64 + q * 8] = *(uint4*)p;
        }
    }
}

// ------------------- fused edge softmax + aggregation ----------------------
__device__ __forceinline__ float leaky_exp(float l) {
    l = l > 0.f ? l : NEG_SLOPE * l;
    return __expf(l);
}
__device__ __forceinline__ float elu(float v) {
    return v > 0.f ? v : expm1f(v);
}

// Layer 1: one warp per dst node; lane covers channels 4l..4l+3 (head l>>3).
__global__ void agg1_kernel(int N, const float* __restrict__ b1) {
    int node = (blockIdx.x * blockDim.x + threadIdx.x) >> 5;
    int lane = threadIdx.x & 31;
    if (node >= N) return;
    int beg = g_off[node], end = g_off[node + 1];
    float4 ad = *(const float4*)&g_adst1[node * 4];
    int head = lane >> 3;
    float a0 = 0.f, a1 = 0.f, a2 = 0.f, a3 = 0.f;
    float s0 = 0.f, s1 = 0.f, s2 = 0.f, s3 = 0.f;
    for (int base = beg; base < end; base += 32) {
        int e = base + lane;
        int src = 0;
        float w0 = 0.f, w1 = 0.f, w2 = 0.f, w3 = 0.f;
        if (e < end) {
            src = g_srcs[e];
            float4 as = *(const float4*)&g_asrc1[src * 4];
            w0 = leaky_exp(as.x + ad.x);
            w1 = leaky_exp(as.y + ad.y);
            w2 = leaky_exp(as.z + ad.z);
            w3 = leaky_exp(as.w + ad.w);
            s0 += w0; s1 += w1; s2 += w2; s3 += w3;
        }
        int cnt = min(32, end - base);
        #pragma unroll 4
        for (int j = 0; j < cnt; j++) {
            int   sj = __shfl_sync(0xffffffffu, src, j);
            float u0 = __shfl_sync(0xffffffffu, w0, j);
            float u1 = __shfl_sync(0xffffffffu, w1, j);
            float u2 = __shfl_sync(0xffffffffu, w2, j);
            float u3 = __shfl_sync(0xffffffffu, w3, j);
            float uw = (head == 0) ? u0 : (head == 1) ? u1 : (head == 2) ? u2 : u3;
            uint2 hv = *(const uint2*)&g_h1h[(long long)sj * 128 + 4 * lane];
            float2 f0 = __half22float2(*(__half2*)&hv.x);
            float2 f1 = __half22float2(*(__half2*)&hv.y);
            a0 += uw * f0.x; a1 += uw * f0.y;
            a2 += uw * f1.x; a3 += uw * f1.y;
        }
    }
    #pragma unroll
    for (int off = 16; off; off >>= 1) {
        s0 += __shfl_xor_sync(0xffffffffu, s0, off);
        s1 += __shfl_xor_sync(0xffffffffu, s1, off);
        s2 += __shfl_xor_sync(0xffffffffu, s2, off);
        s3 += __shfl_xor_sync(0xffffffffu, s3, off);
    }
    float sw = (head == 0) ? s0 : (head == 1) ? s1 : (head == 2) ? s2 : s3;
    float inv = 1.f / (sw + 1e-16f);
    int c0 = 4 * lane;
    float4 bv = *(const float4*)&b1[c0];
    float4 o;
    o.x = elu(a0 * inv + bv.x);
    o.y = elu(a1 * inv + bv.y);
    o.z = elu(a2 * inv + bv.z);
    o.w = elu(a3 * inv + bv.w);
    *(float4*)&g_act1[(long long)node * 128 + c0] = o;
}

// Layer 2: single head. -> d_out (fp32)
__global__ void agg2_kernel(int N, const float* __restrict__ b2,
                            float* __restrict__ out) {
    int node = (blockIdx.x * blockDim.x + threadIdx.x) >> 5;
    int lane = threadIdx.x & 31;
    if (node >= N) return;
    int beg = g_off[node], end = g_off[node + 1];
    float ad = g_adst2[node];
    float a0 = 0.f, a1 = 0.f, a2 = 0.f, a3 = 0.f, s = 0.f;
    for (int base = beg; base < end; base += 32) {
        int e = base + lane;
        int src = 0;
        float w = 0.f;
        if (e < end) {
            src = g_srcs[e];
            w = leaky_exp(g_asrc2[src] + ad);
            s += w;
        }
        int cnt = min(32, end - base);
        #pragma unroll 4
        for (int j = 0; j < cnt; j++) {
            int   sj = __shfl_sync(0xffffffffu, src, j);
            float u  = __shfl_sync(0xffffffffu, w, j);
            uint2 hv = *(const uint2*)&g_h2h[(long long)sj * 128 + 4 * lane];
            float2 f0 = __half22float2(*(__half2*)&hv.x);
            float2 f1 = __half22float2(*(__half2*)&hv.y);
            a0 += u * f0.x; a1 += u * f0.y;
            a2 += u * f1.x; a3 += u * f1.y;
        }
    }
    #pragma unroll
    for (int off = 16; off; off >>= 1)
        s += __shfl_xor_sync(0xffffffffu, s, off);
    float inv = 1.f / (s + 1e-16f);
    int c0 = 4 * lane;
    float4 bv = *(const float4*)&b2[c0];
    float4 o;
    o.x = elu(a0 * inv + bv.x);
    o.y = elu(a1 * inv + bv.y);
    o.z = elu(a2 * inv + bv.z);
    o.w = elu(a3 * inv + bv.w);
    *(float4*)&out[(long long)node * 128 + c0] = o;
}

// ------------------------------- launch ------------------------------------
extern "C" void kernel_launch(void* const* d_in, const int* in_sizes, int n_in,
                              void* d_out, int out_size) {
    const float* x        = (const float*)d_in[0];
    const void*  a        = d_in[1];
    const float* W1       = (const float*)d_in[2];
    const float* att_src1 = (const float*)d_in[3];
    const float* att_dst1 = (const float*)d_in[4];
    const float* b1       = (const float*)d_in[5];
    const float* W2       = (const float*)d_in[6];
    const float* att_src2 = (const float*)d_in[7];
    const float* att_dst2 = (const float*)d_in[8];
    const float* b2       = (const float*)d_in[9];
    float* out = (float*)d_out;

    void *p_h1 = 0, *p_act1 = 0, *p_h2 = 0;
    void *p_w1h = 0, *p_w1l = 0, *p_w2h = 0, *p_w2l = 0;
    cudaGetSymbolAddress(&p_h1, g_h1h);
    cudaGetSymbolAddress(&p_act1, g_act1);
    cudaGetSymbolAddress(&p_h2, g_h2h);
    cudaGetSymbolAddress(&p_w1h, g_w1h);
    cudaGetSymbolAddress(&p_w1l, g_w1l);
    cudaGetSymbolAddress(&p_w2h, g_w2h);
    cudaGetSymbolAddress(&p_w2l, g_w2l);
    __half* h1  = (__half*)p_h1;
    float* act1 = (float*)p_act1;
    __half* h2  = (__half*)p_h2;

    int N = in_sizes[0] / 128;
    int E = in_sizes[1] / 2;

    int eg = (E + 255) / 256;
    int ng = (N + 255) / 256;
    int wg = (N + 7) / 8;
    int gg = (N + 127) / 128;
    int sb = (N + SCAN_CHUNK - 1) / SCAN_CHUNK;

    cudaFuncSetAttribute(wmma_gemm_kernel<4>,
                         cudaFuncAttributeMaxDynamicSharedMemorySize, WG_SMEM);
    cudaFuncSetAttribute(wmma_gemm_kernel<1>,
                         cudaFuncAttributeMaxDynamicSharedMemorySize, WG_SMEM);

    prep_w_kernel<<<64, 256>>>(W1, (__nv_bfloat16*)p_w1h, (__nv_bfloat16*)p_w1l);
    prep_w_kernel<<<64, 256>>>(W2, (__nv_bfloat16*)p_w2h, (__nv_bfloat16*)p_w2l);

    detect_kernel<<<1, 256>>>(a, N);
    zero_cnt_kernel<<<ng, 256>>>(N);
    hist_kernel<<<eg, 256>>>(a, E);
    scanA_kernel<<<sb, 1024>>>(N);
    scanB_kernel<<<1, 32>>>(sb, N);
    scanC_kernel<<<ng, 256>>>(N);
    scatter_kernel<<<eg, 256>>>(a, E);

    // Layer 1
    wmma_gemm_kernel<4><<<gg, 256, WG_SMEM>>>(x, (const __nv_bfloat16*)p_w1h,
                                              (const __nv_bfloat16*)p_w1l,
                                              att_src1, att_dst1, h1, N);
    agg1_kernel<<<wg, 256>>>(N, b1);

    // Layer 2
    wmma_gemm_kernel<1><<<gg, 256, WG_SMEM>>>(act1, (const __nv_bfloat16*)p_w2h,
                                              (const __nv_bfloat16*)p_w2l,
                                              att_src2, att_dst2, h2, N);
    agg2_kernel<<<wg, 256>>>(N, b2, out);
}

// round 14
// speedup vs baseline: 1.1149x; 1.1149x over previous
#include <cuda_runtime.h>
#include <cuda_fp16.h>
#include <cuda_bf16.h>
#include <mma.h>
#include <cstdint>
#include <math.h>

using namespace nvcuda;

// ---------------------------------------------------------------------------
// GAT graph encoder, 2 layers. CSR-by-dst per call; softmax max cancels.
// R8 structure + WMMA-v2 bf16-split GEMM at occupancy 2 (B-lo term streamed
// from global; A hi/lo + B hi in smem). Attention logits fused in epilogue.
// ---------------------------------------------------------------------------

#define NMAX 100000
#define EMAX 1600000
#define NEG_SLOPE 0.2f
#define SCAN_CHUNK 4096
#define LDT 136

typedef unsigned long long ull;

__device__ __half g_h1h[NMAX * 128];
__device__ __half g_h2h[NMAX * 128];
__device__ float  g_act1[NMAX * 128];
__device__ float  g_asrc1[NMAX * 4];
__device__ float  g_adst1[NMAX * 4];
__device__ float  g_asrc2[NMAX];
__device__ float  g_adst2[NMAX];
__device__ int    g_cnt[NMAX];
__device__ int    g_off[NMAX + 1];
__device__ int    g_pos[NMAX];
__device__ int    g_srcs[EMAX];
__device__ int    g_bsum[64];
__device__ int    g_bpre[64];
__device__ int    g_is64;
// W transposed + bf16 hi/lo split: Wt[n][k] = W[k*128+n], row-major 128x128
__device__ __align__(128) __nv_bfloat16 g_w1h[16384];
__device__ __align__(128) __nv_bfloat16 g_w1l[16384];
__device__ __align__(128) __nv_bfloat16 g_w2h[16384];
__device__ __align__(128) __nv_bfloat16 g_w2l[16384];

// smem layout (bytes): A hi | A lo | B hi | att.  C (fp32) aliases A hi+lo.
#define SM_AH   0
#define SM_AL   34816
#define SM_BH   69632
#define SM_ATT  104448
#define WG_SMEM (104448 + 1024)

// --------------------------- edge dtype sniffing ---------------------------
__global__ void detect_kernel(const void* a, int n_nodes) {
    __shared__ int s_bad;
    int i = threadIdx.x;
    if (i == 0) s_bad = 0;
    __syncthreads();
    const ull* p = (const ull*)a;
    if (p[i] >= (ull)n_nodes) atomicAdd(&s_bad, 1);
    __syncthreads();
    if (i == 0) g_is64 = (s_bad == 0) ? 1 : 0;
}

__device__ __forceinline__ int edge_val(const void* a, long long idx) {
    if (g_is64) return (int)((const long long*)a)[idx];
    return ((const int*)a)[idx];
}

// ------------------------------- CSR build ---------------------------------
__global__ void zero_cnt_kernel(int n) {
    int i = blockIdx.x * blockDim.x + threadIdx.x;
    if (i < n) g_cnt[i] = 0;
}

__global__ void scanA_kernel(int n) {
    __shared__ int wsum[32];
    int b = blockIdx.x, tid = threadIdx.x;
    int lane = tid & 31, warp = tid >> 5;
    int base = b * SCAN_CHUNK + tid * 4;
    int v0 = 0, v1 = 0, v2 = 0, v3 = 0;
    if (base + 3 < n) {
        int4 v = *(const int4*)&g_cnt[base];
        v0 = v.x; v1 = v.y; v2 = v.z; v3 = v.w;
    } else if (base < n) {
        v0 = g_cnt[base];
        if (base + 1 < n) v1 = g_cnt[base + 1];
        if (base + 2 < n) v2 = g_cnt[base + 2];
    }
    int tsum = v0 + v1 + v2 + v3;
    int x = tsum;
    #pragma unroll
    for (int d = 1; d < 32; d <<= 1) {
        int t = __shfl_up_sync(0xffffffffu, x, d);
        if (lane >= d) x += t;
    }
    if (lane == 31) wsum[warp] = x;
    __syncthreads();
    if (warp == 0) {
        int y = wsum[lane];
        #pragma unroll
        for (int d = 1; d < 32; d <<= 1) {
            int t = __shfl_up_sync(0xffffffffu, y, d);
            if (lane >= d) y += t;
        }
        wsum[lane] = y;
    }
    __syncthreads();
    int excl = (warp ? wsum[warp - 1] : 0) + (x - tsum);
    if (base < n) {
        g_off[base] = excl;
        if (base + 1 < n) g_off[base + 1] = excl + v0;
        if (base + 2 < n) g_off[base + 2] = excl + v0 + v1;
        if (base + 3 < n) g_off[base + 3] = excl + v0 + v1 + v2;
    }
    if (tid == 0) g_bsum[b] = wsum[31];
}

__global__ void scanB_kernel(int nblocks, int n) {
    int lane = threadIdx.x;
    int v = (lane < nblocks) ? g_bsum[lane] : 0;
    int x = v;
    #pragma unroll
    for (int d = 1; d < 32; d <<= 1) {
        int t = __shfl_up_sync(0xffffffffu, x, d);
        if (lane >= d) x += t;
    }
    if (lane < nblocks) g_bpre[lane] = x - v;
    if (lane == 31) g_off[n] = x;
}

__global__ void scanC_kernel(int n) {
    int i = blockIdx.x * blockDim.x + threadIdx.x;
    if (i < n) {
        int o = g_off[i] + g_bpre[i >> 12];
        g_off[i] = o;
        g_pos[i] = o;
    }
}

__global__ void scatter_kernel(const void* a, int E) {
    int e = blockIdx.x * blockDim.x + threadIdx.x;
    if (e >= E) return;
    int src = edge_val(a, e);
    int dst = edge_val(a, (long long)E + e);
    int p = atomicAdd(&g_pos[dst], 1);
    g_srcs[p] = src;
}

// ----------------------- W -> transposed bf16 split ------------------------
__global__ void prep_w_kernel(const float* __restrict__ W,
                              __nv_bfloat16* __restrict__ Wh,
                              __nv_bfloat16* __restrict__ Wl) {
    int i = blockIdx.x * blockDim.x + threadIdx.x;
    if (i >= 16384) return;
    int k = i >> 7, n = i & 127;
    float v = W[i];
    __nv_bfloat16 hi = __float2bfloat16_rn(v);
    __nv_bfloat16 lo = __float2bfloat16_rn(v - __bfloat162float(hi));
    Wh[n * 128 + k] = hi;
    Wl[n * 128 + k] = lo;
}

// ------------------- WMMA GEMM v2 + attention epilogue ---------------------
// C[128,128] = A @ W via bf16 split (Ahi*Bhi + Ahi*Blo + Alo*Bhi), fp32 acc.
// 8 warps x (32x64) tiles. A hi/lo + B hi in smem; B lo frags from global.
// Blocks >= gemm_blocks instead run the destination histogram (layer1).
template <int HEADS>
__global__ __launch_bounds__(256, 2)
void wmma_gemm_kernel(const float* __restrict__ A,
                      const __nv_bfloat16* __restrict__ WtH,
                      const __nv_bfloat16* __restrict__ WtL,
                      const float* __restrict__ att_src,
                      const float* __restrict__ att_dst,
                      __half* __restrict__ H, int M,
                      int gemm_blocks, const void* ea, int E) {
    extern __shared__ char smem[];

    if (blockIdx.x >= gemm_blocks) {        // histogram side-work
        int e = (blockIdx.x - gemm_blocks) * blockDim.x + threadIdx.x;
        if (e < E) {
            int dst = edge_val(ea, (long long)E + e);
            atomicAdd(&g_cnt[dst], 1);
        }
        return;
    }

    __nv_bfloat16* sAh = (__nv_bfloat16*)(smem + SM_AH);
    __nv_bfloat16* sAl = (__nv_bfloat16*)(smem + SM_AL);
    __nv_bfloat16* sBh = (__nv_bfloat16*)(smem + SM_BH);
    float* satt = (float*)(smem + SM_ATT);
    float* sC = (float*)smem;               // aliases A tiles after mainloop

    int tid = threadIdx.x;
    int row0 = blockIdx.x * 128;

    if (tid < 128) {
        satt[tid] = att_src[tid];
        satt[128 + tid] = att_dst[tid];
    }
    for (int i = tid; i < 2048; i += 256) {
        int r = i >> 4, c = (i & 15) * 8;
        *(uint4*)&sBh[r * LDT + c] = *(const uint4*)&WtH[r * 128 + c];
    }
    for (int i = tid; i < 4096; i += 256) {
        int r = i >> 5, c = (i & 31) * 4;
        float4 v = make_float4(0.f, 0.f, 0.f, 0.f);
        if (row0 + r < M)
            v = *(const float4*)&A[(long long)(row0 + r) * 128 + c];
        float vv[4] = {v.x, v.y, v.z, v.w};
        __nv_bfloat16 hi[4], lo[4];
        #pragma unroll
        for (int q = 0; q < 4; q++) {
            hi[q] = __float2bfloat16_rn(vv[q]);
            lo[q] = __float2bfloat16_rn(vv[q] - __bfloat162float(hi[q]));
        }
        *(uint2*)&sAh[r * LDT + c] = *(uint2*)hi;
        *(uint2*)&sAl[r * LDT + c] = *(uint2*)lo;
    }
    __syncthreads();

    int wid = tid >> 5;
    int wm = wid & 3;
    int wn = wid >> 2;

    wmma::fragment<wmma::accumulator, 16, 16, 16, float> acc[2][4];
    #pragma unroll
    for (int i = 0; i < 2; i++)
        #pragma unroll
        for (int j = 0; j < 4; j++) wmma::fill_fragment(acc[i][j], 0.f);

    #pragma unroll
    for (int k0 = 0; k0 < 128; k0 += 16) {
        wmma::fragment<wmma::matrix_a, 16, 16, 16, __nv_bfloat16, wmma::row_major> ah[2], al[2];
        #pragma unroll
        for (int i = 0; i < 2; i++) {
            wmma::load_matrix_sync(ah[i], &sAh[(wm * 32 + i * 16) * LDT + k0], LDT);
            wmma::load_matrix_sync(al[i], &sAl[(wm * 32 + i * 16) * LDT + k0], LDT);
        }
        #pragma unroll
        for (int j = 0; j < 4; j++) {
            wmma::fragment<wmma::matrix_b, 16, 16, 16, __nv_bfloat16, wmma::col_major> bh, bl;
            wmma::load_matrix_sync(bh, &sBh[(wn * 64 + j * 16) * LDT + k0], LDT);
            wmma::load_matrix_sync(bl, &WtL[(wn * 64 + j * 16) * 128 + k0], 128);
            #pragma unroll
            for (int i = 0; i < 2; i++) {
                wmma::mma_sync(acc[i][j], ah[i], bh, acc[i][j]);
                wmma::mma_sync(acc[i][j], ah[i], bl, acc[i][j]);
                wmma::mma_sync(acc[i][j], al[i], bh, acc[i][j]);
            }
        }
    }
    __syncthreads();

    #pragma unroll
    for (int i = 0; i < 2; i++)
        #pragma unroll
        for (int j = 0; j < 4; j++)
            wmma::store_matrix_sync(&sC[(wm * 32 + i * 16) * LDT + wn * 64 + j * 16],
                                    acc[i][j], LDT, wmma::mem_row_major);
    __syncthreads();

    // Epilogue: each thread handles one half-row (64 cols).
    int lrow = tid >> 1;
    int half = tid & 1;
    int r = row0 + lrow;
    const float* crow = &sC[lrow * LDT + half * 64];

    if (HEADS == 4) {
        #pragma unroll
        for (int hh = 0; hh < 2; hh++) {
            int h = half * 2 + hh;
            float ps = 0.f, pd = 0.f;
            #pragma unroll
            for (int c = 0; c < 32; c++) {
                float v = crow[hh * 32 + c];
                ps += v * satt[h * 32 + c];
                pd += v * satt[128 + h * 32 + c];
            }
            if (r < M) {
                g_asrc1[r * 4 + h] = ps;
                g_adst1[r * 4 + h] = pd;
            }
        }
    } else {
        float ps = 0.f, pd = 0.f;
        #pragma unroll
        for (int c = 0; c < 64; c++) {
            float v = crow[c];
            ps += v * satt[half * 64 + c];
            pd += v * satt[128 + half * 64 + c];
        }
        ps += __shfl_xor_sync(0xffffffffu, ps, 1);
        pd += __shfl_xor_sync(0xffffffffu, pd, 1);
        if (r < M && half == 0) {
            g_asrc2[r] = ps;
            g_adst2[r] = pd;
        }
    }
    if (r < M) {
        #pragma unroll
        for (int q = 0; q < 8; q++) {
            __half2 p[4];
            #pragma unroll
            for (int j = 0; j < 4; j++)
                p[j] = __floats2half2_rn(crow[q * 8 + 2 * j], crow[q * 8 + 2 * j + 1]);
            *(uint4*)&H[(long long)r * 128 + half * 64 + q * 8] = *(uint4*)p;
        }
    }
}

// ------------------- fused edge softmax + aggregation ----------------------
__device__ __forceinline__ float leaky_exp(float l) {
    l = l > 0.f ? l : NEG_SLOPE * l;
    return __expf(l);
}
__device__ __forceinline__ float elu(float v) {
    return v > 0.f ? v : expm1f(v);
}

// Layer 1: one warp per dst node; lane covers channels 4l..4l+3 (head l>>3).
__global__ void agg1_kernel(int N, const float* __restrict__ b1) {
    int node = (blockIdx.x * blockDim.x + threadIdx.x) >> 5;
    int lane = threadIdx.x & 31;
    if (node >= N) return;
    int beg = g_off[node], end = g_off[node + 1];
    float4 ad = *(const float4*)&g_adst1[node * 4];
    int head = lane >> 3;
    float a0 = 0.f, a1 = 0.f, a2 = 0.f, a3 = 0.f;
    float s0 = 0.f, s1 = 0.f, s2 = 0.f, s3 = 0.f;
    for (int base = beg; base < end; base += 32) {
        int e = base + lane;
        int src = 0;
        float w0 = 0.f, w1 = 0.f, w2 = 0.f, w3 = 0.f;
        if (e < end) {
            src = g_srcs[e];
            float4 as = *(const float4*)&g_asrc1[src * 4];
            w0 = leaky_exp(as.x + ad.x);
            w1 = leaky_exp(as.y + ad.y);
            w2 = leaky_exp(as.z + ad.z);
            w3 = leaky_exp(as.w + ad.w);
            s0 += w0; s1 += w1; s2 += w2; s3 += w3;
        }
        int cnt = min(32, end - base);
        #pragma unroll 4
        for (int j = 0; j < cnt; j++) {
            int   sj = __shfl_sync(0xffffffffu, src, j);
            float u0 = __shfl_sync(0xffffffffu, w0, j);
            float u1 = __shfl_sync(0xffffffffu, w1, j);
            float u2 = __shfl_sync(0xffffffffu, w2, j);
            float u3 = __shfl_sync(0xffffffffu, w3, j);
            float uw = (head == 0) ? u0 : (head == 1) ? u1 : (head == 2) ? u2 : u3;
            uint2 hv = *(const uint2*)&g_h1h[(long long)sj * 128 + 4 * lane];
            float2 f0 = __half22float2(*(__half2*)&hv.x);
            float2 f1 = __half22float2(*(__half2*)&hv.y);
            a0 += uw * f0.x; a1 += uw * f0.y;
            a2 += uw * f1.x; a3 += uw * f1.y;
        }
    }
    #pragma unroll
    for (int off = 16; off; off >>= 1) {
        s0 += __shfl_xor_sync(0xffffffffu, s0, off);
        s1 += __shfl_xor_sync(0xffffffffu, s1, off);
        s2 += __shfl_xor_sync(0xffffffffu, s2, off);
        s3 += __shfl_xor_sync(0xffffffffu, s3, off);
    }
    float sw = (head == 0) ? s0 : (head == 1) ? s1 : (head == 2) ? s2 : s3;
    float inv = 1.f / (sw + 1e-16f);
    int c0 = 4 * lane;
    float4 bv = *(const float4*)&b1[c0];
    float4 o;
    o.x = elu(a0 * inv + bv.x);
    o.y = elu(a1 * inv + bv.y);
    o.z = elu(a2 * inv + bv.z);
    o.w = elu(a3 * inv + bv.w);
    *(float4*)&g_act1[(long long)node * 128 + c0] = o;
}

// Layer 2: single head. -> d_out (fp32)
__global__ void agg2_kernel(int N, const float* __restrict__ b2,
                            float* __restrict__ out) {
    int node = (blockIdx.x * blockDim.x + threadIdx.x) >> 5;
    int lane = threadIdx.x & 31;
    if (node >= N) return;
    int beg = g_off[node], end = g_off[node + 1];
    float ad = g_adst2[node];
    float a0 = 0.f, a1 = 0.f, a2 = 0.f, a3 = 0.f, s = 0.f;
    for (int base = beg; base < end; base += 32) {
        int e = base + lane;
        int src = 0;
        float w = 0.f;
        if (e < end) {
            src = g_srcs[e];
            w = leaky_exp(g_asrc2[src] + ad);
            s += w;
        }
        int cnt = min(32, end - base);
        #pragma unroll 4
        for (int j = 0; j < cnt; j++) {
            int   sj = __shfl_sync(0xffffffffu, src, j);
            float u  = __shfl_sync(0xffffffffu, w, j);
            uint2 hv = *(const uint2*)&g_h2h[(long long)sj * 128 + 4 * lane];
            float2 f0 = __half22float2(*(__half2*)&hv.x);
            float2 f1 = __half22float2(*(__half2*)&hv.y);
            a0 += u * f0.x; a1 += u * f0.y;
            a2 += u * f1.x; a3 += u * f1.y;
        }
    }
    #pragma unroll
    for (int off = 16; off; off >>= 1)
        s += __shfl_xor_sync(0xffffffffu, s, off);
    float inv = 1.f / (s + 1e-16f);
    int c0 = 4 * lane;
    float4 bv = *(const float4*)&b2[c0];
    float4 o;
    o.x = elu(a0 * inv + bv.x);
    o.y = elu(a1 * inv + bv.y);
    o.z = elu(a2 * inv + bv.z);
    o.w = elu(a3 * inv + bv.w);
    *(float4*)&out[(long long)node * 128 + c0] = o;
}

// ------------------------------- launch ------------------------------------
extern "C" void kernel_launch(void* const* d_in, const int* in_sizes, int n_in,
                              void* d_out, int out_size) {
    const float* x        = (const float*)d_in[0];
    const void*  a        = d_in[1];
    const float* W1       = (const float*)d_in[2];
    const float* att_src1 = (const float*)d_in[3];
    const float* att_dst1 = (const float*)d_in[4];
    const float* b1       = (const float*)d_in[5];
    const float* W2       = (const float*)d_in[6];
    const float* att_src2 = (const float*)d_in[7];
    const float* att_dst2 = (const float*)d_in[8];
    const float* b2       = (const float*)d_in[9];
    float* out = (float*)d_out;

    void *p_h1 = 0, *p_act1 = 0, *p_h2 = 0;
    void *p_w1h = 0, *p_w1l = 0, *p_w2h = 0, *p_w2l = 0;
    cudaGetSymbolAddress(&p_h1, g_h1h);
    cudaGetSymbolAddress(&p_act1, g_act1);
    cudaGetSymbolAddress(&p_h2, g_h2h);
    cudaGetSymbolAddress(&p_w1h, g_w1h);
    cudaGetSymbolAddress(&p_w1l, g_w1l);
    cudaGetSymbolAddress(&p_w2h, g_w2h);
    cudaGetSymbolAddress(&p_w2l, g_w2l);
    __half* h1  = (__half*)p_h1;
    float* act1 = (float*)p_act1;
    __half* h2  = (__half*)p_h2;

    int N = in_sizes[0] / 128;
    int E = in_sizes[1] / 2;

    int eg = (E + 255) / 256;
    int ng = (N + 255) / 256;
    int wg = (N + 7) / 8;
    int gg = (N + 127) / 128;
    int sb = (N + SCAN_CHUNK - 1) / SCAN_CHUNK;

    cudaFuncSetAttribute(wmma_gemm_kernel<4>,
                         cudaFuncAttributeMaxDynamicSharedMemorySize, WG_SMEM);
    cudaFuncSetAttribute(wmma_gemm_kernel<1>,
                         cudaFuncAttributeMaxDynamicSharedMemorySize, WG_SMEM);

    prep_w_kernel<<<64, 256>>>(W1, (__nv_bfloat16*)p_w1h, (__nv_bfloat16*)p_w1l);
    prep_w_kernel<<<64, 256>>>(W2, (__nv_bfloat16*)p_w2h, (__nv_bfloat16*)p_w2l);

    detect_kernel<<<1, 256>>>(a, N);
    zero_cnt_kernel<<<ng, 256>>>(N);

    // Layer 1 GEMM with fused destination histogram in trailing blocks
    wmma_gemm_kernel<4><<<gg + eg, 256, WG_SMEM>>>(
        x, (const __nv_bfloat16*)p_w1h, (const __nv_bfloat16*)p_w1l,
        att_src1, att_dst1, h1, N, gg, a, E);
    scanA_kernel<<<sb, 1024>>>(N);
    scanB_kernel<<<1, 32>>>(sb, N);
    scanC_kernel<<<ng, 256>>>(N);
    scatter_kernel<<<eg, 256>>>(a, E);

    agg1_kernel<<<wg, 256>>>(N, b1);

    // Layer 2
    wmma_gemm_kernel<1><<<gg, 256, WG_SMEM>>>(
        act1, (const __nv_bfloat16*)p_w2h, (const __nv_bfloat16*)p_w2l,
        att_src2, att_dst2, h2, N, gg, (const void*)0, 0);

    agg2_kernel<<<wg, 256>>>(N, b2, out);
}

// round 15
// speedup vs baseline: 1.2144x; 1.0892x over previous
#include <cuda_runtime.h>
#include <cuda_fp16.h>
#include <cstdint>
#include <math.h>

// ---------------------------------------------------------------------------
// GAT graph encoder, 2 layers. CSR-by-dst per call; softmax max cancels.
// R8 baseline (f32x2 GEMM + fused att logits, fp16 h gathers) with:
//  - gemm1 moved to 4th launch (ncu capture slot) for profiling
//  - agg1 weights staged via smem broadcast instead of 5x shfl
//  - scanB folded into scanC
// ---------------------------------------------------------------------------

#define NMAX 100000
#define EMAX 1600000
#define NEG_SLOPE 0.2f
#define SCAN_CHUNK 4096

typedef unsigned long long ull;

__device__ __half g_h1h[NMAX * 128];
__device__ __half g_h2h[NMAX * 128];
__device__ float  g_act1[NMAX * 128];
__device__ float  g_asrc1[NMAX * 4];
__device__ float  g_adst1[NMAX * 4];
__device__ float  g_asrc2[NMAX];
__device__ float  g_adst2[NMAX];
__device__ int    g_cnt[NMAX];
__device__ int    g_off[NMAX + 1];
__device__ int    g_pos[NMAX];
__device__ int    g_srcs[EMAX];
__device__ int    g_bsum[64];
__device__ int    g_is64;

// ------------------------- packed fp32 helpers -----------------------------
__device__ __forceinline__ ull f32x2_bcast(float a) {
    ull d;
    asm("mov.b64 %0, {%1, %1};" : "=l"(d) : "f"(a));
    return d;
}
__device__ __forceinline__ ull f32x2_fma(ull a, ull b, ull c) {
    ull d;
    asm("fma.rn.f32x2 %0, %1, %2, %3;" : "=l"(d) : "l"(a), "l"(b), "l"(c));
    return d;
}
__device__ __forceinline__ float2 f32x2_unpack(ull p) {
    float2 r;
    asm("mov.b64 {%0, %1}, %2;" : "=f"(r.x), "=f"(r.y) : "l"(p));
    return r;
}

// --------------------------- edge dtype sniffing ---------------------------
__global__ void detect_kernel(const void* a, int n_nodes) {
    __shared__ int s_bad;
    int i = threadIdx.x;
    if (i == 0) s_bad = 0;
    __syncthreads();
    const ull* p = (const ull*)a;
    if (p[i] >= (ull)n_nodes) atomicAdd(&s_bad, 1);
    __syncthreads();
    if (i == 0) g_is64 = (s_bad == 0) ? 1 : 0;
}

__device__ __forceinline__ int edge_val(const void* a, long long idx) {
    if (g_is64) return (int)((const long long*)a)[idx];
    return ((const int*)a)[idx];
}

// ------------------------------- CSR build ---------------------------------
__global__ void zero_cnt_kernel(int n) {
    int i = blockIdx.x * blockDim.x + threadIdx.x;
    if (i < n) g_cnt[i] = 0;
}

__global__ void hist_kernel(const void* a, int E) {
    int e = blockIdx.x * blockDim.x + threadIdx.x;
    if (e >= E) return;
    int dst = edge_val(a, (long long)E + e);
    atomicAdd(&g_cnt[dst], 1);
}

// Phase A: per-block local exclusive scan (4 elems/thread) + block sums.
__global__ void scanA_kernel(int n) {
    __shared__ int wsum[32];
    int b = blockIdx.x, tid = threadIdx.x;
    int lane = tid & 31, warp = tid >> 5;
    int base = b * SCAN_CHUNK + tid * 4;
    int v0 = 0, v1 = 0, v2 = 0, v3 = 0;
    if (base + 3 < n) {
        int4 v = *(const int4*)&g_cnt[base];
        v0 = v.x; v1 = v.y; v2 = v.z; v3 = v.w;
    } else if (base < n) {
        v0 = g_cnt[base];
        if (base + 1 < n) v1 = g_cnt[base + 1];
        if (base + 2 < n) v2 = g_cnt[base + 2];
    }
    int tsum = v0 + v1 + v2 + v3;
    int x = tsum;
    #pragma unroll
    for (int d = 1; d < 32; d <<= 1) {
        int t = __shfl_up_sync(0xffffffffu, x, d);
        if (lane >= d) x += t;
    }
    if (lane == 31) wsum[warp] = x;
    __syncthreads();
    if (warp == 0) {
        int y = wsum[lane];
        #pragma unroll
        for (int d = 1; d < 32; d <<= 1) {
            int t = __shfl_up_sync(0xffffffffu, y, d);
            if (lane >= d) y += t;
        }
        wsum[lane] = y;
    }
    __syncthreads();
    int excl = (warp ? wsum[warp - 1] : 0) + (x - tsum);
    if (base < n) {
        g_off[base] = excl;
        if (base + 1 < n) g_off[base + 1] = excl + v0;
        if (base + 2 < n) g_off[base + 2] = excl + v0 + v1;
        if (base + 3 < n) g_off[base + 3] = excl + v0 + v1 + v2;
    }
    if (tid == 0) g_bsum[b] = wsum[31];
}

// Phase C (with B folded in): every block warp-scans the <=32 block sums,
// adds its chunk prefix, fills cursor copy; block 0 writes g_off[n].
__global__ void scanC_kernel(int n, int nblocks) {
    __shared__ int s_pre[32];
    int tid = threadIdx.x;
    if (tid < 32) {
        int v = (tid < nblocks) ? g_bsum[tid] : 0;
        int x = v;
        #pragma unroll
        for (int d = 1; d < 32; d <<= 1) {
            int t = __shfl_up_sync(0xffffffffu, x, d);
            if (tid >= d) x += t;
        }
        s_pre[tid] = x - v;
        if (tid == 31 && blockIdx.x == 0) g_off[n] = x;
    }
    __syncthreads();
    int i = blockIdx.x * blockDim.x + tid;
    if (i < n) {
        int o = g_off[i] + s_pre[i >> 12];
        g_off[i] = o;
        g_pos[i] = o;
    }
}

__global__ void scatter_kernel(const void* a, int E) {
    int e = blockIdx.x * blockDim.x + threadIdx.x;
    if (e >= E) return;
    int src = edge_val(a, e);
    int dst = edge_val(a, (long long)E + e);
    int p = atomicAdd(&g_pos[dst], 1);
    g_srcs[p] = src;
}

// --------------------- GEMM (f32x2) + attention epilogue -------------------
// C[M,128] = A[M,128] @ W[128,128], fp32 via packed fma.rn.f32x2.
// Writes h (fp16) + per-node attention logits (fp32). HEADS = 4 or 1.
template <int HEADS>
__global__ void gemm_att_kernel(const float* __restrict__ A,
                                const float* __restrict__ W,
                                const float* __restrict__ att_src,
                                const float* __restrict__ att_dst,
                                __half* __restrict__ H, int M) {
    __shared__ float As[16][132];
    __shared__ float Ws[16][128];
    int t = threadIdx.x;
    int tx = t & 15;
    int ty = t >> 4;
    int row0 = blockIdx.x * 128;
    ull acc2[8][4];
    #pragma unroll
    for (int m = 0; m < 8; m++)
        #pragma unroll
        for (int p = 0; p < 4; p++) acc2[m][p] = 0ull;

    for (int k0 = 0; k0 < 128; k0 += 16) {
        #pragma unroll
        for (int i = 0; i < 2; i++) {
            int idx = t + i * 256;
            int r = idx >> 2;
            int c4 = idx & 3;
            float4 v = make_float4(0.f, 0.f, 0.f, 0.f);
            if (row0 + r < M)
                v = *(const float4*)&A[(long long)(row0 + r) * 128 + k0 + c4 * 4];
            As[c4 * 4 + 0][r] = v.x;
            As[c4 * 4 + 1][r] = v.y;
            As[c4 * 4 + 2][r] = v.z;
            As[c4 * 4 + 3][r] = v.w;
        }
        #pragma unroll
        for (int i = 0; i < 2; i++) {
            int idx = t + i * 256;
            int r = idx >> 5;
            int c4 = idx & 31;
            *(float4*)&Ws[r][c4 * 4] = *(const float4*)&W[(k0 + r) * 128 + c4 * 4];
        }
        __syncthreads();
        #pragma unroll
        for (int k = 0; k < 16; k++) {
            ulonglong2 b01 = *(const ulonglong2*)&Ws[k][tx * 8];
            ulonglong2 b23 = *(const ulonglong2*)&Ws[k][tx * 8 + 4];
            ull bp[4] = {b01.x, b01.y, b23.x, b23.y};
            float4 a0 = *(const float4*)&As[k][ty * 8];
            float4 a1 = *(const float4*)&As[k][ty * 8 + 4];
            float av[8] = {a0.x, a0.y, a0.z, a0.w, a1.x, a1.y, a1.z, a1.w};
            #pragma unroll
            for (int m = 0; m < 8; m++) {
                ull am = f32x2_bcast(av[m]);
                #pragma unroll
                for (int p = 0; p < 4; p++)
                    acc2[m][p] = f32x2_fma(am, bp[p], acc2[m][p]);
            }
        }
        __syncthreads();
    }

    float acc[8][8];
    #pragma unroll
    for (int m = 0; m < 8; m++)
        #pragma unroll
        for (int p = 0; p < 4; p++) {
            float2 v = f32x2_unpack(acc2[m][p]);
            acc[m][2 * p] = v.x;
            acc[m][2 * p + 1] = v.y;
        }

    float avs[8], avd[8];
    #pragma unroll
    for (int n = 0; n < 8; n++) {
        avs[n] = att_src[tx * 8 + n];
        avd[n] = att_dst[tx * 8 + n];
    }
    #pragma unroll
    for (int m = 0; m < 8; m++) {
        int r = row0 + ty * 8 + m;
        float ps = 0.f, pd = 0.f;
        #pragma unroll
        for (int n = 0; n < 8; n++) {
            ps += acc[m][n] * avs[n];
            pd += acc[m][n] * avd[n];
        }
        if (HEADS == 4) {
            #pragma unroll
            for (int off = 1; off <= 2; off <<= 1) {
                ps += __shfl_xor_sync(0xffffffffu, ps, off);
                pd += __shfl_xor_sync(0xffffffffu, pd, off);
            }
            if ((tx & 3) == 0 && r < M) {
                g_asrc1[r * 4 + (tx >> 2)] = ps;
                g_adst1[r * 4 + (tx >> 2)] = pd;
            }
        } else {
            #pragma unroll
            for (int off = 1; off <= 8; off <<= 1) {
                ps += __shfl_xor_sync(0xffffffffu, ps, off);
                pd += __shfl_xor_sync(0xffffffffu, pd, off);
            }
            if (tx == 0 && r < M) {
                g_asrc2[r] = ps;
                g_adst2[r] = pd;
            }
        }
        if (r < M) {
            __half hh[8];
            #pragma unroll
            for (int q = 0; q < 8; q++) hh[q] = __float2half_rn(acc[m][q]);
            *(uint4*)&H[(long long)r * 128 + tx * 8] = *(uint4*)hh;
        }
    }
}

// ------------------- fused edge softmax + aggregation ----------------------
__device__ __forceinline__ float leaky_exp(float l) {
    l = l > 0.f ? l : NEG_SLOPE * l;
    return __expf(l);
}
__device__ __forceinline__ float elu(float v) {
    return v > 0.f ? v : expm1f(v);
}

// Layer 1: one warp per dst node; lane covers channels 4l..4l+3 (head l>>3).
// Edge weights staged through smem (broadcast LDS) instead of 5x shfl.
__global__ void agg1_kernel(int N, const float* __restrict__ b1) {
    __shared__ float s_w[8][33 * 4];   // per-warp 32 float4 slots (+pad)
    __shared__ int   s_s[8][32];
    int wwid = threadIdx.x >> 5;
    int node = (blockIdx.x * blockDim.x + threadIdx.x) >> 5;
    int lane = threadIdx.x & 31;
    if (node >= N) return;
    int beg = g_off[node], end = g_off[node + 1];
    float4 ad = *(const float4*)&g_adst1[node * 4];
    int head = lane >> 3;
    float a0 = 0.f, a1 = 0.f, a2 = 0.f, a3 = 0.f;
    float s0 = 0.f, s1 = 0.f, s2 = 0.f, s3 = 0.f;
    for (int base = beg; base < end; base += 32) {
        int e = base + lane;
        int src = 0;
        float w0 = 0.f, w1 = 0.f, w2 = 0.f, w3 = 0.f;
        if (e < end) {
            src = g_srcs[e];
            float4 as = *(const float4*)&g_asrc1[src * 4];
            w0 = leaky_exp(as.x + ad.x);
            w1 = leaky_exp(as.y + ad.y);
            w2 = leaky_exp(as.z + ad.z);
            w3 = leaky_exp(as.w + ad.w);
            s0 += w0; s1 += w1; s2 += w2; s3 += w3;
        }
        *(float4*)&s_w[wwid][lane * 4] = make_float4(w0, w1, w2, w3);
        s_s[wwid][lane] = src;
        __syncwarp();
        int cnt = min(32, end - base);
        #pragma unroll 4
        for (int j = 0; j < cnt; j++) {
            int   sj = s_s[wwid][j];
            float uw = s_w[wwid][j * 4 + head];
            uint2 hv = *(const uint2*)&g_h1h[(long long)sj * 128 + 4 * lane];
            float2 f0 = __half22float2(*(__half2*)&hv.x);
            float2 f1 = __half22float2(*(__half2*)&hv.y);
            a0 += uw * f0.x; a1 += uw * f0.y;
            a2 += uw * f1.x; a3 += uw * f1.y;
        }
        __syncwarp();
    }
    #pragma unroll
    for (int off = 16; off; off >>= 1) {
        s0 += __shfl_xor_sync(0xffffffffu, s0, off);
        s1 += __shfl_xor_sync(0xffffffffu, s1, off);
        s2 += __shfl_xor_sync(0xffffffffu, s2, off);
        s3 += __shfl_xor_sync(0xffffffffu, s3, off);
    }
    float sw = (head == 0) ? s0 : (head == 1) ? s1 : (head == 2) ? s2 : s3;
    float inv = 1.f / (sw + 1e-16f);
    int c0 = 4 * lane;
    float4 bv = *(const float4*)&b1[c0];
    float4 o;
    o.x = elu(a0 * inv + bv.x);
    o.y = elu(a1 * inv + bv.y);
    o.z = elu(a2 * inv + bv.z);
    o.w = elu(a3 * inv + bv.w);
    *(float4*)&g_act1[(long long)node * 128 + c0] = o;
}

// Layer 2: single head. -> d_out (fp32)
__global__ void agg2_kernel(int N, const float* __restrict__ b2,
                            float* __restrict__ out) {
    int node = (blockIdx.x * blockDim.x + threadIdx.x) >> 5;
    int lane = threadIdx.x & 31;
    if (node >= N) return;
    int beg = g_off[node], end = g_off[node + 1];
    float ad = g_adst2[node];
    float a0 = 0.f, a1 = 0.f, a2 = 0.f, a3 = 0.f, s = 0.f;
    for (int base = beg; base < end; base += 32) {
        int e = base + lane;
        int src = 0;
        float w = 0.f;
        if (e < end) {
            src = g_srcs[e];
            w = leaky_exp(g_asrc2[src] + ad);
            s += w;
        }
        int cnt = min(32, end - base);
        #pragma unroll 4
        for (int j = 0; j < cnt; j++) {
            int   sj = __shfl_sync(0xffffffffu, src, j);
            float u  = __shfl_sync(0xffffffffu, w, j);
            uint2 hv = *(const uint2*)&g_h2h[(long long)sj * 128 + 4 * lane];
            float2 f0 = __half22float2(*(__half2*)&hv.x);
            float2 f1 = __half22float2(*(__half2*)&hv.y);
            a0 += u * f0.x; a1 += u * f0.y;
            a2 += u * f1.x; a3 += u * f1.y;
        }
    }
    #pragma unroll
    for (int off = 16; off; off >>= 1)
        s += __shfl_xor_sync(0xffffffffu, s, off);
    float inv = 1.f / (s + 1e-16f);
    int c0 = 4 * lane;
    float4 bv = *(const float4*)&b2[c0];
    float4 o;
    o.x = elu(a0 * inv + bv.x);
    o.y = elu(a1 * inv + bv.y);
    o.z = elu(a2 * inv + bv.z);
    o.w = elu(a3 * inv + bv.w);
    *(float4*)&out[(long long)node * 128 + c0] = o;
}

// ------------------------------- launch ------------------------------------
extern "C" void kernel_launch(void* const* d_in, const int* in_sizes, int n_in,
                              void* d_out, int out_size) {
    const float* x        = (const float*)d_in[0];
    const void*  a        = d_in[1];
    const float* W1       = (const float*)d_in[2];
    const float* att_src1 = (const float*)d_in[3];
    const float* att_dst1 = (const float*)d_in[4];
    const float* b1       = (const float*)d_in[5];
    const float* W2       = (const float*)d_in[6];
    const float* att_src2 = (const float*)d_in[7];
    const float* att_dst2 = (const float*)d_in[8];
    const float* b2       = (const float*)d_in[9];
    float* out = (float*)d_out;

    void *p_h1 = 0, *p_act1 = 0, *p_h2 = 0;
    cudaGetSymbolAddress(&p_h1, g_h1h);
    cudaGetSymbolAddress(&p_act1, g_act1);
    cudaGetSymbolAddress(&p_h2, g_h2h);
    __half* h1  = (__half*)p_h1;
    float* act1 = (float*)p_act1;
    __half* h2  = (__half*)p_h2;

    int N = in_sizes[0] / 128;
    int E = in_sizes[1] / 2;

    int eg = (E + 255) / 256;
    int ng = (N + 255) / 256;
    int wg = (N + 7) / 8;
    int gg = (N + 127) / 128;
    int sb = (N + SCAN_CHUNK - 1) / SCAN_CHUNK;

    detect_kernel<<<1, 256>>>(a, N);                 // 1
    zero_cnt_kernel<<<ng, 256>>>(N);                 // 2
    hist_kernel<<<eg, 256>>>(a, E);                  // 3
    // 4th launch = gemm1: lands in the ncu capture slot.
    gemm_att_kernel<4><<<gg, 256>>>(x, W1, att_src1, att_dst1, h1, N);
    scanA_kernel<<<sb, 1024>>>(N);                   // 5
    scanC_kernel<<<ng, 256>>>(N, sb);                // 6 (scanB folded in)
    scatter_kernel<<<eg, 256>>>(a, E);               // 7
    agg1_kernel<<<wg, 256>>>(N, b1);                 // 8
    gemm_att_kernel<1><<<gg, 256>>>(act1, W2, att_src2, att_dst2, h2, N); // 9
    agg2_kernel<<<wg, 256>>>(N, b2, out);            // 10
}

// round 16
// speedup vs baseline: 1.3475x; 1.1096x over previous
#include <cuda_runtime.h>
#include <cuda_fp16.h>
#include <cstdint>
#include <math.h>

// ---------------------------------------------------------------------------
// GAT graph encoder, 2 layers. CSR-by-dst per call; softmax max cancels.
// R15 + graph fork/join: CSR-build branch runs on a side stream concurrent
// with gemm1 inside the captured graph.
// ---------------------------------------------------------------------------

#define NMAX 100000
#define EMAX 1600000
#define NEG_SLOPE 0.2f
#define SCAN_CHUNK 4096

typedef unsigned long long ull;

__device__ __half g_h1h[NMAX * 128];
__device__ __half g_h2h[NMAX * 128];
__device__ float  g_act1[NMAX * 128];
__device__ float  g_asrc1[NMAX * 4];
__device__ float  g_adst1[NMAX * 4];
__device__ float  g_asrc2[NMAX];
__device__ float  g_adst2[NMAX];
__device__ int    g_cnt[NMAX];
__device__ int    g_off[NMAX + 1];
__device__ int    g_pos[NMAX];
__device__ int    g_srcs[EMAX];
__device__ int    g_bsum[64];
__device__ int    g_is64;

// ------------------------- packed fp32 helpers -----------------------------
__device__ __forceinline__ ull f32x2_bcast(float a) {
    ull d;
    asm("mov.b64 %0, {%1, %1};" : "=l"(d) : "f"(a));
    return d;
}
__device__ __forceinline__ ull f32x2_fma(ull a, ull b, ull c) {
    ull d;
    asm("fma.rn.f32x2 %0, %1, %2, %3;" : "=l"(d) : "l"(a), "l"(b), "l"(c));
    return d;
}
__device__ __forceinline__ float2 f32x2_unpack(ull p) {
    float2 r;
    asm("mov.b64 {%0, %1}, %2;" : "=f"(r.x), "=f"(r.y) : "l"(p));
    return r;
}

// --------------------------- edge dtype sniffing ---------------------------
__global__ void detect_kernel(const void* a, int n_nodes) {
    __shared__ int s_bad;
    int i = threadIdx.x;
    if (i == 0) s_bad = 0;
    __syncthreads();
    const ull* p = (const ull*)a;
    if (p[i] >= (ull)n_nodes) atomicAdd(&s_bad, 1);
    __syncthreads();
    if (i == 0) g_is64 = (s_bad == 0) ? 1 : 0;
}

__device__ __forceinline__ int edge_val(const void* a, long long idx) {
    if (g_is64) return (int)((const long long*)a)[idx];
    return ((const int*)a)[idx];
}

// ------------------------------- CSR build ---------------------------------
__global__ void zero_cnt_kernel(int n) {
    int i = blockIdx.x * blockDim.x + threadIdx.x;
    if (i < n) g_cnt[i] = 0;
}

__global__ void hist_kernel(const void* a, int E) {
    int e = blockIdx.x * blockDim.x + threadIdx.x;
    if (e >= E) return;
    int dst = edge_val(a, (long long)E + e);
    atomicAdd(&g_cnt[dst], 1);
}

// Phase A: per-block local exclusive scan (4 elems/thread) + block sums.
__global__ void scanA_kernel(int n) {
    __shared__ int wsum[32];
    int b = blockIdx.x, tid = threadIdx.x;
    int lane = tid & 31, warp = tid >> 5;
    int base = b * SCAN_CHUNK + tid * 4;
    int v0 = 0, v1 = 0, v2 = 0, v3 = 0;
    if (base + 3 < n) {
        int4 v = *(const int4*)&g_cnt[base];
        v0 = v.x; v1 = v.y; v2 = v.z; v3 = v.w;
    } else if (base < n) {
        v0 = g_cnt[base];
        if (base + 1 < n) v1 = g_cnt[base + 1];
        if (base + 2 < n) v2 = g_cnt[base + 2];
    }
    int tsum = v0 + v1 + v2 + v3;
    int x = tsum;
    #pragma unroll
    for (int d = 1; d < 32; d <<= 1) {
        int t = __shfl_up_sync(0xffffffffu, x, d);
        if (lane >= d) x += t;
    }
    if (lane == 31) wsum[warp] = x;
    __syncthreads();
    if (warp == 0) {
        int y = wsum[lane];
        #pragma unroll
        for (int d = 1; d < 32; d <<= 1) {
            int t = __shfl_up_sync(0xffffffffu, y, d);
            if (lane >= d) y += t;
        }
        wsum[lane] = y;
    }
    __syncthreads();
    int excl = (warp ? wsum[warp - 1] : 0) + (x - tsum);
    if (base < n) {
        g_off[base] = excl;
        if (base + 1 < n) g_off[base + 1] = excl + v0;
        if (base + 2 < n) g_off[base + 2] = excl + v0 + v1;
        if (base + 3 < n) g_off[base + 3] = excl + v0 + v1 + v2;
    }
    if (tid == 0) g_bsum[b] = wsum[31];
}

// Phase C (B folded in): each block warp-scans the <=32 block sums, adds its
// chunk prefix, fills cursor copy; block 0 writes g_off[n].
__global__ void scanC_kernel(int n, int nblocks) {
    __shared__ int s_pre[32];
    int tid = threadIdx.x;
    if (tid < 32) {
        int v = (tid < nblocks) ? g_bsum[tid] : 0;
        int x = v;
        #pragma unroll
        for (int d = 1; d < 32; d <<= 1) {
            int t = __shfl_up_sync(0xffffffffu, x, d);
            if (tid >= d) x += t;
        }
        s_pre[tid] = x - v;
        if (tid == 31 && blockIdx.x == 0) g_off[n] = x;
    }
    __syncthreads();
    int i = blockIdx.x * blockDim.x + tid;
    if (i < n) {
        int o = g_off[i] + s_pre[i >> 12];
        g_off[i] = o;
        g_pos[i] = o;
    }
}

__global__ void scatter_kernel(const void* a, int E) {
    int e = blockIdx.x * blockDim.x + threadIdx.x;
    if (e >= E) return;
    int src = edge_val(a, e);
    int dst = edge_val(a, (long long)E + e);
    int p = atomicAdd(&g_pos[dst], 1);
    g_srcs[p] = src;
}

// --------------------- GEMM (f32x2) + attention epilogue -------------------
template <int HEADS>
__global__ void gemm_att_kernel(const float* __restrict__ A,
                                const float* __restrict__ W,
                                const float* __restrict__ att_src,
                                const float* __restrict__ att_dst,
                                __half* __restrict__ H, int M) {
    __shared__ float As[16][132];
    __shared__ float Ws[16][128];
    int t = threadIdx.x;
    int tx = t & 15;
    int ty = t >> 4;
    int row0 = blockIdx.x * 128;
    ull acc2[8][4];
    #pragma unroll
    for (int m = 0; m < 8; m++)
        #pragma unroll
        for (int p = 0; p < 4; p++) acc2[m][p] = 0ull;

    for (int k0 = 0; k0 < 128; k0 += 16) {
        #pragma unroll
        for (int i = 0; i < 2; i++) {
            int idx = t + i * 256;
            int r = idx >> 2;
            int c4 = idx & 3;
            float4 v = make_float4(0.f, 0.f, 0.f, 0.f);
            if (row0 + r < M)
                v = *(const float4*)&A[(long long)(row0 + r) * 128 + k0 + c4 * 4];
            As[c4 * 4 + 0][r] = v.x;
            As[c4 * 4 + 1][r] = v.y;
            As[c4 * 4 + 2][r] = v.z;
            As[c4 * 4 + 3][r] = v.w;
        }
        #pragma unroll
        for (int i = 0; i < 2; i++) {
            int idx = t + i * 256;
            int r = idx >> 5;
            int c4 = idx & 31;
            *(float4*)&Ws[r][c4 * 4] = *(const float4*)&W[(k0 + r) * 128 + c4 * 4];
        }
        __syncthreads();
        #pragma unroll
        for (int k = 0; k < 16; k++) {
            ulonglong2 b01 = *(const ulonglong2*)&Ws[k][tx * 8];
            ulonglong2 b23 = *(const ulonglong2*)&Ws[k][tx * 8 + 4];
            ull bp[4] = {b01.x, b01.y, b23.x, b23.y};
            float4 a0 = *(const float4*)&As[k][ty * 8];
            float4 a1 = *(const float4*)&As[k][ty * 8 + 4];
            float av[8] = {a0.x, a0.y, a0.z, a0.w, a1.x, a1.y, a1.z, a1.w};
            #pragma unroll
            for (int m = 0; m < 8; m++) {
                ull am = f32x2_bcast(av[m]);
                #pragma unroll
                for (int p = 0; p < 4; p++)
                    acc2[m][p] = f32x2_fma(am, bp[p], acc2[m][p]);
            }
        }
        __syncthreads();
    }

    float acc[8][8];
    #pragma unroll
    for (int m = 0; m < 8; m++)
        #pragma unroll
        for (int p = 0; p < 4; p++) {
            float2 v = f32x2_unpack(acc2[m][p]);
            acc[m][2 * p] = v.x;
            acc[m][2 * p + 1] = v.y;
        }

    float avs[8], avd[8];
    #pragma unroll
    for (int n = 0; n < 8; n++) {
        avs[n] = att_src[tx * 8 + n];
        avd[n] = att_dst[tx * 8 + n];
    }
    #pragma unroll
    for (int m = 0; m < 8; m++) {
        int r = row0 + ty * 8 + m;
        float ps = 0.f, pd = 0.f;
        #pragma unroll
        for (int n = 0; n < 8; n++) {
            ps += acc[m][n] * avs[n];
            pd += acc[m][n] * avd[n];
        }
        if (HEADS == 4) {
            #pragma unroll
            for (int off = 1; off <= 2; off <<= 1) {
                ps += __shfl_xor_sync(0xffffffffu, ps, off);
                pd += __shfl_xor_sync(0xffffffffu, pd, off);
            }
            if ((tx & 3) == 0 && r < M) {
                g_asrc1[r * 4 + (tx >> 2)] = ps;
                g_adst1[r * 4 + (tx >> 2)] = pd;
            }
        } else {
            #pragma unroll
            for (int off = 1; off <= 8; off <<= 1) {
                ps += __shfl_xor_sync(0xffffffffu, ps, off);
                pd += __shfl_xor_sync(0xffffffffu, pd, off);
            }
            if (tx == 0 && r < M) {
                g_asrc2[r] = ps;
                g_adst2[r] = pd;
            }
        }
        if (r < M) {
            __half hh[8];
            #pragma unroll
            for (int q = 0; q < 8; q++) hh[q] = __float2half_rn(acc[m][q]);
            *(uint4*)&H[(long long)r * 128 + tx * 8] = *(uint4*)hh;
        }
    }
}

// ------------------- fused edge softmax + aggregation ----------------------
__device__ __forceinline__ float leaky_exp(float l) {
    l = l > 0.f ? l : NEG_SLOPE * l;
    return __expf(l);
}
__device__ __forceinline__ float elu(float v) {
    return v > 0.f ? v : expm1f(v);
}

// Layer 1: one warp per dst node; weights staged via smem broadcast.
__global__ void agg1_kernel(int N, const float* __restrict__ b1) {
    __shared__ float s_w[8][33 * 4];
    __shared__ int   s_s[8][32];
    int wwid = threadIdx.x >> 5;
    int node = (blockIdx.x * blockDim.x + threadIdx.x) >> 5;
    int lane = threadIdx.x & 31;
    if (node >= N) return;
    int beg = g_off[node], end = g_off[node + 1];
    float4 ad = *(const float4*)&g_adst1[node * 4];
    int head = lane >> 3;
    float a0 = 0.f, a1 = 0.f, a2 = 0.f, a3 = 0.f;
    float s0 = 0.f, s1 = 0.f, s2 = 0.f, s3 = 0.f;
    for (int base = beg; base < end; base += 32) {
        int e = base + lane;
        int src = 0;
        float w0 = 0.f, w1 = 0.f, w2 = 0.f, w3 = 0.f;
        if (e < end) {
            src = g_srcs[e];
            float4 as = *(const float4*)&g_asrc1[src * 4];
            w0 = leaky_exp(as.x + ad.x);
            w1 = leaky_exp(as.y + ad.y);
            w2 = leaky_exp(as.z + ad.z);
            w3 = leaky_exp(as.w + ad.w);
            s0 += w0; s1 += w1; s2 += w2; s3 += w3;
        }
        *(float4*)&s_w[wwid][lane * 4] = make_float4(w0, w1, w2, w3);
        s_s[wwid][lane] = src;
        __syncwarp();
        int cnt = min(32, end - base);
        #pragma unroll 4
        for (int j = 0; j < cnt; j++) {
            int   sj = s_s[wwid][j];
            float uw = s_w[wwid][j * 4 + head];
            uint2 hv = *(const uint2*)&g_h1h[(long long)sj * 128 + 4 * lane];
            float2 f0 = __half22float2(*(__half2*)&hv.x);
            float2 f1 = __half22float2(*(__half2*)&hv.y);
            a0 += uw * f0.x; a1 += uw * f0.y;
            a2 += uw * f1.x; a3 += uw * f1.y;
        }
        __syncwarp();
    }
    #pragma unroll
    for (int off = 16; off; off >>= 1) {
        s0 += __shfl_xor_sync(0xffffffffu, s0, off);
        s1 += __shfl_xor_sync(0xffffffffu, s1, off);
        s2 += __shfl_xor_sync(0xffffffffu, s2, off);
        s3 += __shfl_xor_sync(0xffffffffu, s3, off);
    }
    float sw = (head == 0) ? s0 : (head == 1) ? s1 : (head == 2) ? s2 : s3;
    float inv = 1.f / (sw + 1e-16f);
    int c0 = 4 * lane;
    float4 bv = *(const float4*)&b1[c0];
    float4 o;
    o.x = elu(a0 * inv + bv.x);
    o.y = elu(a1 * inv + bv.y);
    o.z = elu(a2 * inv + bv.z);
    o.w = elu(a3 * inv + bv.w);
    *(float4*)&g_act1[(long long)node * 128 + c0] = o;
}

// Layer 2: single head. -> d_out (fp32)
__global__ void agg2_kernel(int N, const float* __restrict__ b2,
                            float* __restrict__ out) {
    int node = (blockIdx.x * blockDim.x + threadIdx.x) >> 5;
    int lane = threadIdx.x & 31;
    if (node >= N) return;
    int beg = g_off[node], end = g_off[node + 1];
    float ad = g_adst2[node];
    float a0 = 0.f, a1 = 0.f, a2 = 0.f, a3 = 0.f, s = 0.f;
    for (int base = beg; base < end; base += 32) {
        int e = base + lane;
        int src = 0;
        float w = 0.f;
        if (e < end) {
            src = g_srcs[e];
            w = leaky_exp(g_asrc2[src] + ad);
            s += w;
        }
        int cnt = min(32, end - base);
        #pragma unroll 4
        for (int j = 0; j < cnt; j++) {
            int   sj = __shfl_sync(0xffffffffu, src, j);
            float u  = __shfl_sync(0xffffffffu, w, j);
            uint2 hv = *(const uint2*)&g_h2h[(long long)sj * 128 + 4 * lane];
            float2 f0 = __half22float2(*(__half2*)&hv.x);
            float2 f1 = __half22float2(*(__half2*)&hv.y);
            a0 += u * f0.x; a1 += u * f0.y;
            a2 += u * f1.x; a3 += u * f1.y;
        }
    }
    #pragma unroll
    for (int off = 16; off; off >>= 1)
        s += __shfl_xor_sync(0xffffffffu, s, off);
    float inv = 1.f / (s + 1e-16f);
    int c0 = 4 * lane;
    float4 bv = *(const float4*)&b2[c0];
    float4 o;
    o.x = elu(a0 * inv + bv.x);
    o.y = elu(a1 * inv + bv.y);
    o.z = elu(a2 * inv + bv.z);
    o.w = elu(a3 * inv + bv.w);
    *(float4*)&out[(long long)node * 128 + c0] = o;
}

// ------------------------------- launch ------------------------------------
extern "C" void kernel_launch(void* const* d_in, const int* in_sizes, int n_in,
                              void* d_out, int out_size) {
    const float* x        = (const float*)d_in[0];
    const void*  a        = d_in[1];
    const float* W1       = (const float*)d_in[2];
    const float* att_src1 = (const float*)d_in[3];
    const float* att_dst1 = (const float*)d_in[4];
    const float* b1       = (const float*)d_in[5];
    const float* W2       = (const float*)d_in[6];
    const float* att_src2 = (const float*)d_in[7];
    const float* att_dst2 = (const float*)d_in[8];
    const float* b2       = (const float*)d_in[9];
    float* out = (float*)d_out;

    void *p_h1 = 0, *p_act1 = 0, *p_h2 = 0;
    cudaGetSymbolAddress(&p_h1, g_h1h);
    cudaGetSymbolAddress(&p_act1, g_act1);
    cudaGetSymbolAddress(&p_h2, g_h2h);
    __half* h1  = (__half*)p_h1;
    float* act1 = (float*)p_act1;
    __half* h2  = (__half*)p_h2;

    int N = in_sizes[0] / 128;
    int E = in_sizes[1] / 2;

    int eg = (E + 255) / 256;
    int ng = (N + 255) / 256;
    int wg = (N + 7) / 8;
    int gg = (N + 127) / 128;
    int sb = (N + SCAN_CHUNK - 1) / SCAN_CHUNK;

    // One-time side-stream + events (created on the first, non-captured,
    // correctness call; reused under capture — all fork/join ops are
    // graph-capturable and no device memory is allocated).
    static cudaStream_t s2 = 0;
    static cudaEvent_t evFork = 0, evJoin = 0;
    if (!s2) {
        cudaStreamCreateWithFlags(&s2, cudaStreamNonBlocking);
        cudaEventCreateWithFlags(&evFork, cudaEventDisableTiming);
        cudaEventCreateWithFlags(&evJoin, cudaEventDisableTiming);
    }

    // Fork: CSR-build branch on s2, concurrent with gemm1 on the main stream.
    cudaEventRecord(evFork, (cudaStream_t)0);
    cudaStreamWaitEvent(s2, evFork, 0);
    detect_kernel<<<1, 256, 0, s2>>>(a, N);
    zero_cnt_kernel<<<ng, 256, 0, s2>>>(N);
    hist_kernel<<<eg, 256, 0, s2>>>(a, E);
    scanA_kernel<<<sb, 1024, 0, s2>>>(N);
    scanC_kernel<<<ng, 256, 0, s2>>>(N, sb);
    scatter_kernel<<<eg, 256, 0, s2>>>(a, E);
    cudaEventRecord(evJoin, s2);

    // Main stream: layer-1 GEMM overlaps the CSR branch.
    gemm_att_kernel<4><<<gg, 256>>>(x, W1, att_src1, att_dst1, h1, N);

    // Join: agg1 needs both gemm1 and the CSR.
    cudaStreamWaitEvent((cudaStream_t)0, evJoin, 0);
    agg1_kernel<<<wg, 256>>>(N, b1);
    gemm_att_kernel<1><<<gg, 256>>>(act1, W2, att_src2, att_dst2, h2, N);
    agg2_kernel<<<wg, 256>>>(N, b2, out);
}